// round 1
// baseline (speedup 1.0000x reference)
#include <cuda_runtime.h>

#define IN_CH 16
#define OUT_CH 64
#define H 32
#define W 32
#define NB 8
#define KHW 9
#define F (IN_CH * KHW)      // 144
#define OCG 16               // out channels per block
#define ROWS 8               // output rows per block
#define TPB 256              // 8 rows * 32 cols

__global__ __launch_bounds__(TPB) void normdist_kernel(
    const float* __restrict__ x,      // (8,16,32,32)
    const float* __restrict__ weight, // (64,144)
    const float* __restrict__ bias,   // (64)
    float* __restrict__ out)          // (8,64,32,32)
{
    const int og   = blockIdx.x;          // 0..3 out-channel group
    const int rg   = blockIdx.y;          // 0..3 row group
    const int n    = blockIdx.z;          // 0..7 batch
    const int tid  = threadIdx.x;
    const int r    = tid >> 5;            // 0..7 row within tile
    const int cpos = tid & 31;            // 0..31 col

    const int row0 = rg * ROWS;

    // xs[c][rr][cc]: padded tile, rr in [0,10) maps to global row row0-1+rr,
    // cc in [0,34) maps to global col cc-1. Zero outside.
    __shared__ float xs[IN_CH][ROWS + 2][W + 2];
    __shared__ __align__(16) float wT[F][OCG];   // transposed weight chunk

    // ---- load weight chunk transposed: wT[f][oo] = weight[(og*16+oo)*144 + f]
    for (int idx = tid; idx < F * OCG; idx += TPB) {
        int oo = idx / F;
        int f  = idx % F;
        wT[f][oo] = weight[(og * OCG + oo) * F + f];
    }

    // ---- load x tile with halo (zero padding)
    const float* xn = x + (size_t)n * IN_CH * H * W;
    const int tile_elems = IN_CH * (ROWS + 2) * (W + 2);  // 16*10*34 = 5440
    for (int idx = tid; idx < tile_elems; idx += TPB) {
        int c   = idx / ((ROWS + 2) * (W + 2));
        int rem = idx % ((ROWS + 2) * (W + 2));
        int rr  = rem / (W + 2);
        int cc  = rem % (W + 2);
        int gr  = row0 - 1 + rr;
        int gc  = cc - 1;
        float v = 0.0f;
        if (gr >= 0 && gr < H && gc >= 0 && gc < W)
            v = xn[(c * H + gr) * W + gc];
        xs[c][rr][cc] = v;
    }
    __syncthreads();

    float acc[OCG];
    #pragma unroll
    for (int o = 0; o < OCG; o++) acc[o] = 0.0f;   // |.| >= 0, so 0 is a safe init

    #pragma unroll 4
    for (int c = 0; c < IN_CH; c++) {
        // gather 3x3 patch into registers
        float p[KHW];
        #pragma unroll
        for (int i = 0; i < 3; i++)
            #pragma unroll
            for (int j = 0; j < 3; j++)
                p[i * 3 + j] = xs[c][r + i][cpos + j];

        #pragma unroll
        for (int j = 0; j < KHW; j++) {
            const int f = c * KHW + j;
            const float4* w4 = reinterpret_cast<const float4*>(&wT[f][0]);
            float4 wa = w4[0], wb = w4[1], wc = w4[2], wd = w4[3];
            const float pj = p[j];
            acc[ 0] = fmaxf(acc[ 0], fabsf(pj - wa.x));
            acc[ 1] = fmaxf(acc[ 1], fabsf(pj - wa.y));
            acc[ 2] = fmaxf(acc[ 2], fabsf(pj - wa.z));
            acc[ 3] = fmaxf(acc[ 3], fabsf(pj - wa.w));
            acc[ 4] = fmaxf(acc[ 4], fabsf(pj - wb.x));
            acc[ 5] = fmaxf(acc[ 5], fabsf(pj - wb.y));
            acc[ 6] = fmaxf(acc[ 6], fabsf(pj - wb.z));
            acc[ 7] = fmaxf(acc[ 7], fabsf(pj - wb.w));
            acc[ 8] = fmaxf(acc[ 8], fabsf(pj - wc.x));
            acc[ 9] = fmaxf(acc[ 9], fabsf(pj - wc.y));
            acc[10] = fmaxf(acc[10], fabsf(pj - wc.z));
            acc[11] = fmaxf(acc[11], fabsf(pj - wc.w));
            acc[12] = fmaxf(acc[12], fabsf(pj - wd.x));
            acc[13] = fmaxf(acc[13], fabsf(pj - wd.y));
            acc[14] = fmaxf(acc[14], fabsf(pj - wd.z));
            acc[15] = fmaxf(acc[15], fabsf(pj - wd.w));
        }
    }

    // ---- write out: out[n][og*16+oo][row0+r][cpos]
    const int orow = row0 + r;
    float* outp = out + (((size_t)n * OUT_CH + og * OCG) * H + orow) * W + cpos;
    #pragma unroll
    for (int o = 0; o < OCG; o++) {
        outp[(size_t)o * H * W] = acc[o] + bias[og * OCG + o];
    }
}

extern "C" void kernel_launch(void* const* d_in, const int* in_sizes, int n_in,
                              void* d_out, int out_size) {
    const float* x      = (const float*)d_in[0];
    const float* weight = (const float*)d_in[1];
    const float* bias   = (const float*)d_in[2];
    float* out          = (float*)d_out;

    dim3 grid(OUT_CH / OCG, H / ROWS, NB);   // (4, 4, 8) = 128 blocks
    normdist_kernel<<<grid, TPB>>>(x, weight, bias, out);
}